// round 12
// baseline (speedup 1.0000x reference)
#include <cuda_runtime.h>
#include <cuda_fp16.h>
#include <cstdint>
#include <math.h>

#define NN   256
#define HWN  196
#define CC   512
#define NBLK  392
#define MROWS 128
#define EPS_POS_F 0.65f
#define EPS_NEG_F 0.40f
#define INV_TAU   (1.0f/0.03f)
#define TEMP_F    0.07f

// ---- smem layout (bytes): 2-stage, all double-buffered ----
#define SM_A(st)    ((st) * 20480)             // audio fp16: 256 x 80B
#define SM_BST(st)  (40960 + (st) * 18432)     // frame fp32 staging: 128 x 144B
#define SM_BF16(st) (77824 + (st) * 10240)     // frame fp16: 128 x 80B
#define SM_RNS      98304                      // float[128]
#define SM_SNUM     98816                      // float[2][256]
#define SM_SDEN     100864                     // float[2][256]
#define SM_SNEG     102912                     // float[4]
#define SMEM_TOTAL  102928

// ---- scratch globals ----
__device__ __half g_aH[NN * CC];          // normalized audio fp16
__device__ float g_pn2[NBLK * 2 * NN];
__device__ float g_pd2[NBLK * 2 * NN];
__device__ float g_qn2[NBLK * 2];
__device__ float g_qd2[NBLK * 2];
__device__ unsigned g_ctr;                // completion counter (self-resetting)

__device__ __forceinline__ uint32_t smem_u32(const void* p) {
    uint32_t a;
    asm("{ .reg .u64 t; cvta.to.shared.u64 t, %1; cvt.u32.u64 %0, t; }" : "=r"(a) : "l"(p));
    return a;
}

#define CP_ASYNC16(dst, src) \
    asm volatile("cp.async.cg.shared.global [%0], [%1], 16;" :: "r"(dst), "l"(src) : "memory")
#define CP_COMMIT() asm volatile("cp.async.commit_group;" ::: "memory")
#define CP_WAIT1()  asm volatile("cp.async.wait_group 1;" ::: "memory")

// fp16 MMA with fp16 accumulators
#define MMA_FP16ACC(d, a, b0, b1)                                               \
    asm volatile("mma.sync.aligned.m16n8k16.row.col.f16.f16.f16.f16 "           \
        "{%0,%1}, {%2,%3,%4,%5}, {%6,%7}, {%0,%1};"                             \
        : "+r"((d)[0]), "+r"((d)[1])                                            \
        : "r"((a)[0]), "r"((a)[1]), "r"((a)[2]), "r"((a)[3]), "r"(b0), "r"(b1))

#define LDSM_X4(r, addr)                                                        \
    asm volatile("ldmatrix.sync.aligned.m8n8.x4.shared.b16 {%0,%1,%2,%3}, [%4];" \
        : "=r"((r)[0]), "=r"((r)[1]), "=r"((r)[2]), "=r"((r)[3]) : "r"(addr))

#define LDSM_X2(r0, r1, addr)                                                   \
    asm volatile("ldmatrix.sync.aligned.m8n8.x2.shared.b16 {%0,%1}, [%2];"      \
        : "=r"(r0), "=r"(r1) : "r"(addr))

// ---------------------------------------------------------------------------
// Kernel A: normalize audio -> fp16 row-major [k][c]
// ---------------------------------------------------------------------------
__global__ void k_audio(const float* __restrict__ audio) {
    int k = blockIdx.x;
    int tid = threadIdx.x;  // 128
    float4 v = *(const float4*)(audio + (size_t)k * CC + tid * 4);
    float ss = v.x * v.x + v.y * v.y + v.z * v.z + v.w * v.w;
#pragma unroll
    for (int o = 16; o; o >>= 1) ss += __shfl_xor_sync(0xffffffffu, ss, o);
    __shared__ float sred[4];
    if ((tid & 31) == 0) sred[tid >> 5] = ss;
    __syncthreads();
    float rn = rsqrtf(sred[0] + sred[1] + sred[2] + sred[3]);
    __half2 p0 = __float22half2_rn(make_float2(v.x * rn, v.y * rn));
    __half2 p1 = __float22half2_rn(make_float2(v.z * rn, v.w * rn));
    uint2 u;
    u.x = *reinterpret_cast<uint32_t*>(&p0);
    u.y = *reinterpret_cast<uint32_t*>(&p1);
    *(uint2*)(g_aH + (size_t)k * CC + tid * 4) = u;
}

// ---------------------------------------------------------------------------
// Main: CTA b computes S[flat rows b*128..+128, audio 0..255] via fp16 MMA,
// fused sigmoid reductions. The LAST CTA to finish (atomic counter) performs
// the rowreduce + loss tail in-kernel and writes the final scalar.
// ---------------------------------------------------------------------------
__global__ void __launch_bounds__(256, 2) k_mainTC(const float* __restrict__ frame,
                                                   float* __restrict__ out) {
    extern __shared__ char sm[];
    uint32_t sb = smem_u32(sm);
    int tid = threadIdx.x;
    int lane = tid & 31;
    int w = tid >> 5;
    int gID = lane >> 2;
    int tig = lane & 3;
    int blk = blockIdx.x;          // 0..391

    const float* fbase = frame + (size_t)blk * MROWS * CC;
    int m_off = (w >> 2) * 64;     // 2 m-groups of 64 rows
    int n_off = (w & 3) * 64;      // 4 n-groups of 64 audio cols

    // ldmatrix per-lane row/col selectors
    int arow = (lane & 7) + ((lane >> 3) & 1) * 8;
    int acol = (lane >> 4) * 16;
    int brow = lane & 7;
    int bcol = ((lane >> 3) & 1) * 16;

#define ISSUE(CH) do {                                                              \
    int _c = (CH);                                                                   \
    if (_c < 16) {                                                                   \
        int _st = _c & 1;                                                            \
        int _c0 = _c * 32;                                                           \
        uint32_t _a = sb + SM_A(_st);                                                \
        uint32_t _b = sb + SM_BST(_st);                                              \
        _Pragma("unroll")                                                            \
        for (int j = 0; j < 4; j++) {                                                \
            int i = tid + j * 256;                                                   \
            int r = i >> 2, s = i & 3;                                               \
            CP_ASYNC16(_a + r * 80 + s * 16, g_aH + (size_t)r * CC + _c0 + s * 8);   \
        }                                                                            \
        _Pragma("unroll")                                                            \
        for (int j = 0; j < 4; j++) {                                                \
            int i = tid + j * 256;                                                   \
            int r = i >> 3, s = i & 7;                                               \
            CP_ASYNC16(_b + r * 144 + s * 16, fbase + (size_t)r * CC + _c0 + s * 4); \
        }                                                                            \
    }                                                                                \
    CP_COMMIT();                                                                     \
} while (0)

    ISSUE(0); ISSUE(1);

    uint32_t acc[4][8][2];     // [mt][nt][half] f16x2
#pragma unroll
    for (int mt = 0; mt < 4; mt++)
#pragma unroll
        for (int nt = 0; nt < 8; nt++) { acc[mt][nt][0] = 0u; acc[mt][nt][1] = 0u; }
    float nrm[4];
#pragma unroll
    for (int j = 0; j < 4; j++) nrm[j] = 0.f;

    for (int ch = 0; ch < 16; ch++) {
        int st = ch & 1;
        CP_WAIT1();
        __syncthreads();

        // ---- convert fp32 staging -> fp16 + row-norm partials ----
#pragma unroll
        for (int j = 0; j < 4; j++) {
            int i = tid + j * 256;
            int r = i >> 3, s = i & 7;
            float4 v = *(const float4*)(sm + SM_BST(st) + r * 144 + s * 16);
            __half2 h01 = __float22half2_rn(make_float2(v.x, v.y));
            __half2 h23 = __float22half2_rn(make_float2(v.z, v.w));
            uint2 u;
            u.x = *reinterpret_cast<uint32_t*>(&h01);
            u.y = *reinterpret_cast<uint32_t*>(&h23);
            *(uint2*)(sm + SM_BF16(st) + r * 80 + s * 8) = u;
            nrm[j] += v.x * v.x + v.y * v.y + v.z * v.z + v.w * v.w;
        }
        __syncthreads();

        // ---- MMA: 2 k16-steps, operands via ldmatrix ----
        uint32_t Abase = sb + (uint32_t)SM_BF16(st);
        uint32_t Bbase = sb + (uint32_t)SM_A(st);
#pragma unroll
        for (int ks = 0; ks < 2; ks++) {
            uint32_t a[4][4];
#pragma unroll
            for (int mt = 0; mt < 4; mt++) {
                uint32_t ad = Abase + (uint32_t)((m_off + mt * 16 + arow) * 80 + ks * 32 + acol);
                LDSM_X4(a[mt], ad);
            }
#pragma unroll
            for (int nt = 0; nt < 8; nt++) {
                uint32_t b0, b1;
                uint32_t bd = Bbase + (uint32_t)((n_off + nt * 8 + brow) * 80 + ks * 32 + bcol);
                LDSM_X2(b0, b1, bd);
#pragma unroll
                for (int mt = 0; mt < 4; mt++) MMA_FP16ACC(acc[mt][nt], a[mt], b0, b1);
            }
        }
        __syncthreads();
        ISSUE(ch + 2);
    }

    // ---- finalize frame row norms ----
    float* rns  = (float*)(sm + SM_RNS);
    float* snum = (float*)(sm + SM_SNUM);
    float* sden = (float*)(sm + SM_SDEN);
    float* sneg = (float*)(sm + SM_SNEG);
#pragma unroll
    for (int j = 0; j < 4; j++) {
        float v = nrm[j];
        v += __shfl_xor_sync(0xffffffffu, v, 1, 8);
        v += __shfl_xor_sync(0xffffffffu, v, 2, 8);
        v += __shfl_xor_sync(0xffffffffu, v, 4, 8);
        if ((tid & 7) == 0) rns[(tid >> 3) + j * 32] = rsqrtf(v);
    }
    snum[tid] = 0.f; snum[256 + tid] = 0.f;
    sden[tid] = 0.f; sden[256 + tid] = 0.f;
    if (tid < 4) sneg[tid] = 0.f;
    __syncthreads();

    // ---- fused sigmoid epilogue with 2-segment split ----
    int n_first = (blk * MROWS) / HWN;
    int nsplit  = (n_first + 1) * HWN - blk * MROWS;
    float qn0 = 0.f, qd0 = 0.f, qn1 = 0.f, qd1 = 0.f;

#pragma unroll
    for (int nt = 0; nt < 8; nt++) {
        float p[2][2] = {{0.f, 0.f}, {0.f, 0.f}};   // [e][seg]
        float d[2][2] = {{0.f, 0.f}, {0.f, 0.f}};
        int kbase = n_off + nt * 8 + tig * 2;
#pragma unroll
        for (int mt = 0; mt < 4; mt++) {
#pragma unroll
            for (int half = 0; half < 2; half++) {
                int row = m_off + mt * 16 + gID + half * 8;
                uint32_t pk = acc[mt][nt][half];
                float2 fv = __half22float2(*reinterpret_cast<__half2*>(&pk));
                float rn = rns[row];
                int seg = (row >= nsplit) ? 1 : 0;
                int nrow = n_first + seg;
#pragma unroll
                for (int e = 0; e < 2; e++) {
                    float S = (e ? fv.y : fv.x) * rn;
                    float wg = __fdividef(1.f, 1.f + __expf((EPS_POS_F - S) * INV_TAU));
                    p[e][seg] += wg * S;
                    d[e][seg] += wg;
                    if (kbase + e == nrow) {
                        float sp = __fdividef(1.f, 1.f + __expf((EPS_NEG_F - S) * INV_TAU));
                        float ng = 1.f - sp;
                        if (seg) { qn1 += ng * S; qd1 += ng; }
                        else     { qn0 += ng * S; qd0 += ng; }
                    }
                }
            }
        }
#pragma unroll
        for (int e = 0; e < 2; e++) {
#pragma unroll
            for (int o = 4; o < 32; o <<= 1) {
                p[e][0] += __shfl_xor_sync(0xffffffffu, p[e][0], o);
                d[e][0] += __shfl_xor_sync(0xffffffffu, d[e][0], o);
                p[e][1] += __shfl_xor_sync(0xffffffffu, p[e][1], o);
                d[e][1] += __shfl_xor_sync(0xffffffffu, d[e][1], o);
            }
            if (lane < 4) {
                int k = kbase + e;
                atomicAdd(&snum[k], p[e][0]);
                atomicAdd(&sden[k], d[e][0]);
                atomicAdd(&snum[256 + k], p[e][1]);
                atomicAdd(&sden[256 + k], d[e][1]);
            }
        }
    }
#pragma unroll
    for (int o = 1; o < 32; o <<= 1) {
        qn0 += __shfl_xor_sync(0xffffffffu, qn0, o);
        qd0 += __shfl_xor_sync(0xffffffffu, qd0, o);
        qn1 += __shfl_xor_sync(0xffffffffu, qn1, o);
        qd1 += __shfl_xor_sync(0xffffffffu, qd1, o);
    }
    if (lane == 0) {
        atomicAdd(&sneg[0], qn0); atomicAdd(&sneg[1], qd0);
        atomicAdd(&sneg[2], qn1); atomicAdd(&sneg[3], qd1);
    }
    __syncthreads();
    g_pn2[(size_t)blk * 512 + tid]       = snum[tid];
    g_pn2[(size_t)blk * 512 + 256 + tid] = snum[256 + tid];
    g_pd2[(size_t)blk * 512 + tid]       = sden[tid];
    g_pd2[(size_t)blk * 512 + 256 + tid] = sden[256 + tid];
    if (tid == 0) {
        g_qn2[blk * 2]     = sneg[0];
        g_qd2[blk * 2]     = sneg[1];
        g_qn2[blk * 2 + 1] = sneg[2];
        g_qd2[blk * 2 + 1] = sneg[3];
    }

    // ======================= fused tail (last CTA only) =====================
    __threadfence();
    __shared__ unsigned s_last;
    if (tid == 0) s_last = (atomicAdd(&g_ctr, 1u) == (unsigned)(NBLK - 1)) ? 1u : 0u;
    __syncthreads();
    if (!s_last) return;
    if (tid == 0) g_ctr = 0;       // reset for next graph replay
    __threadfence();

    // ---- phase 1: rowreduce. thread t = n. ----
    float* sE = snum;               // reuse smem: exp(Nid[k])
    {
        int n = tid;
        int r0 = n * HWN;
        int b0 = r0 >> 7;
        int b1 = (r0 + HWN - 1) >> 7;
        float qn = 0.f, qd = 0.f;
        for (int b = b0; b <= b1; b++) {
            int nf = (b << 7) / HWN;
            int seg = (n == nf) ? 0 : 1;
            qn += g_qn2[b * 2 + seg];
            qd += g_qd2[b * 2 + seg];
        }
        float sumr = 0.f, PiN = 0.f, PiD = 0.f;
        for (int k4 = 0; k4 < NN; k4 += 4) {
            float4 nu = make_float4(0.f, 0.f, 0.f, 0.f);
            float4 de = make_float4(0.f, 0.f, 0.f, 0.f);
#pragma unroll 3
            for (int b = b0; b <= b1; b++) {
                int nf = (b << 7) / HWN;
                int seg = (n == nf) ? 0 : 1;
                float4 a = *(const float4*)&g_pn2[(size_t)b * 512 + seg * 256 + k4];
                float4 c = *(const float4*)&g_pd2[(size_t)b * 512 + seg * 256 + k4];
                nu.x += a.x; nu.y += a.y; nu.z += a.z; nu.w += a.w;
                de.x += c.x; de.y += c.y; de.z += c.z; de.w += c.w;
            }
            float nus[4] = {nu.x, nu.y, nu.z, nu.w};
            float des[4] = {de.x, de.y, de.z, de.w};
#pragma unroll
            for (int e = 0; e < 4; e++) {
                int k = k4 + e;
                float ratio = nus[e] / des[e];
                if (k == n) { PiN = nus[e]; PiD = des[e]; sumr += ratio * (-99.f); }
                else sumr += ratio;
            }
        }
        float Pid = TEMP_F * (PiN / PiD);
        float Nid = TEMP_F * (qn / qd + sumr);
        sE[n] = __expf(Nid);
        sden[n] = __expf(-Pid);     // reuse: e^{-Pid[n]}
    }
    __syncthreads();

    // ---- phase 2: loss = (1/N) sum_{n,k} log(1 + E[k] * e^{-Pid[n]}) ----
    {
        float Pn = sden[tid];
        float acc2 = 0.f;
#pragma unroll 8
        for (int k = 0; k < NN; k++) acc2 += __logf(1.f + sE[k] * Pn);
#pragma unroll
        for (int o = 16; o; o >>= 1) acc2 += __shfl_xor_sync(0xffffffffu, acc2, o);
        if (lane == 0) sneg[0 + 0] = 0.f;   // (not used; keep smem writes simple)
        __shared__ float sred2[8];
        if (lane == 0) sred2[w] = acc2;
        __syncthreads();
        if (tid == 0) {
            float s = 0.f;
#pragma unroll
            for (int i = 0; i < 8; i++) s += sred2[i];
            out[0] = s * (1.0f / NN);
        }
    }
}

extern "C" void kernel_launch(void* const* d_in, const int* in_sizes, int n_in,
                              void* d_out, int out_size) {
    const float* frame = (const float*)d_in[0];
    const float* audio = (const float*)d_in[1];
    if (n_in >= 2 && in_sizes[0] < in_sizes[1]) {
        frame = (const float*)d_in[1];
        audio = (const float*)d_in[0];
    }
    float* out = (float*)d_out;

    cudaFuncSetAttribute(k_mainTC, cudaFuncAttributeMaxDynamicSharedMemorySize, SMEM_TOTAL);

    k_audio<<<NN, 128>>>(audio);
    k_mainTC<<<NBLK, 256, SMEM_TOTAL>>>(frame, out);
}

// round 13
// speedup vs baseline: 1.4184x; 1.4184x over previous
#include <cuda_runtime.h>
#include <cuda_fp16.h>
#include <cstdint>
#include <math.h>

#define NN   256
#define HWN  196
#define CC   512
#define NBLK  392
#define MROWS 128
#define EPS_POS_F 0.65f
#define EPS_NEG_F 0.40f
#define INV_TAU   (1.0f/0.03f)
#define TEMP_F    0.07f

// ---- smem layout (bytes): 2-stage, all double-buffered ----
#define SM_A(st)    ((st) * 20480)             // audio fp16: 256 x 80B
#define SM_BST(st)  (40960 + (st) * 18432)     // frame fp32 staging: 128 x 144B
#define SM_BF16(st) (77824 + (st) * 10240)     // frame fp16: 128 x 80B
#define SM_RNS      98304                      // float[128]
#define SM_SNUM     98816                      // float[2][256]
#define SM_SDEN     100864                     // float[2][256]
#define SM_SNEG     102912                     // float[4]
#define SMEM_TOTAL  102928

// ---- scratch globals ----
__device__ __half g_aH[NN * CC];          // normalized audio fp16
__device__ float g_pn2[NBLK * 2 * NN];
__device__ float g_pd2[NBLK * 2 * NN];
__device__ float g_qn2[NBLK * 2];
__device__ float g_qd2[NBLK * 2];
__device__ unsigned g_ctr;                // completion counter (self-resetting)

__device__ __forceinline__ uint32_t smem_u32(const void* p) {
    uint32_t a;
    asm("{ .reg .u64 t; cvta.to.shared.u64 t, %1; cvt.u32.u64 %0, t; }" : "=r"(a) : "l"(p));
    return a;
}

#define CP_ASYNC16(dst, src) \
    asm volatile("cp.async.cg.shared.global [%0], [%1], 16;" :: "r"(dst), "l"(src) : "memory")
#define CP_COMMIT() asm volatile("cp.async.commit_group;" ::: "memory")
#define CP_WAIT1()  asm volatile("cp.async.wait_group 1;" ::: "memory")

// fp16 MMA with fp16 accumulators
#define MMA_FP16ACC(d, a, b0, b1)                                               \
    asm volatile("mma.sync.aligned.m16n8k16.row.col.f16.f16.f16.f16 "           \
        "{%0,%1}, {%2,%3,%4,%5}, {%6,%7}, {%0,%1};"                             \
        : "+r"((d)[0]), "+r"((d)[1])                                            \
        : "r"((a)[0]), "r"((a)[1]), "r"((a)[2]), "r"((a)[3]), "r"(b0), "r"(b1))

#define LDSM_X4(r, addr)                                                        \
    asm volatile("ldmatrix.sync.aligned.m8n8.x4.shared.b16 {%0,%1,%2,%3}, [%4];" \
        : "=r"((r)[0]), "=r"((r)[1]), "=r"((r)[2]), "=r"((r)[3]) : "r"(addr))

#define LDSM_X2(r0, r1, addr)                                                   \
    asm volatile("ldmatrix.sync.aligned.m8n8.x2.shared.b16 {%0,%1}, [%2];"      \
        : "=r"(r0), "=r"(r1) : "r"(addr))

// ---------------------------------------------------------------------------
// Kernel A: normalize audio -> fp16 row-major [k][c]
// ---------------------------------------------------------------------------
__global__ void k_audio(const float* __restrict__ audio) {
    int k = blockIdx.x;
    int tid = threadIdx.x;  // 128
    float4 v = *(const float4*)(audio + (size_t)k * CC + tid * 4);
    float ss = v.x * v.x + v.y * v.y + v.z * v.z + v.w * v.w;
#pragma unroll
    for (int o = 16; o; o >>= 1) ss += __shfl_xor_sync(0xffffffffu, ss, o);
    __shared__ float sred[4];
    if ((tid & 31) == 0) sred[tid >> 5] = ss;
    __syncthreads();
    float rn = rsqrtf(sred[0] + sred[1] + sred[2] + sred[3]);
    __half2 p0 = __float22half2_rn(make_float2(v.x * rn, v.y * rn));
    __half2 p1 = __float22half2_rn(make_float2(v.z * rn, v.w * rn));
    uint2 u;
    u.x = *reinterpret_cast<uint32_t*>(&p0);
    u.y = *reinterpret_cast<uint32_t*>(&p1);
    *(uint2*)(g_aH + (size_t)k * CC + tid * 4) = u;
}

// ---------------------------------------------------------------------------
// Main: CTA b computes S[flat rows b*128..+128, audio 0..255] via fp16 MMA,
// fused sigmoid reductions. The LAST CTA (atomic counter) performs the
// rowreduce + loss tail in-kernel. NO minBlocks clause: register cap at 128
// caused mainloop spills (round-12 regression, regs=128, L1 18%).
// ---------------------------------------------------------------------------
__global__ void __launch_bounds__(256) k_mainTC(const float* __restrict__ frame,
                                                float* __restrict__ out) {
    extern __shared__ char sm[];
    uint32_t sb = smem_u32(sm);
    int tid = threadIdx.x;
    int lane = tid & 31;
    int w = tid >> 5;
    int gID = lane >> 2;
    int tig = lane & 3;
    int blk = blockIdx.x;          // 0..391

    const float* fbase = frame + (size_t)blk * MROWS * CC;
    int m_off = (w >> 2) * 64;     // 2 m-groups of 64 rows
    int n_off = (w & 3) * 64;      // 4 n-groups of 64 audio cols

    // ldmatrix per-lane row/col selectors
    int arow = (lane & 7) + ((lane >> 3) & 1) * 8;
    int acol = (lane >> 4) * 16;
    int brow = lane & 7;
    int bcol = ((lane >> 3) & 1) * 16;

#define ISSUE(CH) do {                                                              \
    int _c = (CH);                                                                   \
    if (_c < 16) {                                                                   \
        int _st = _c & 1;                                                            \
        int _c0 = _c * 32;                                                           \
        uint32_t _a = sb + SM_A(_st);                                                \
        uint32_t _b = sb + SM_BST(_st);                                              \
        _Pragma("unroll")                                                            \
        for (int j = 0; j < 4; j++) {                                                \
            int i = tid + j * 256;                                                   \
            int r = i >> 2, s = i & 3;                                               \
            CP_ASYNC16(_a + r * 80 + s * 16, g_aH + (size_t)r * CC + _c0 + s * 8);   \
        }                                                                            \
        _Pragma("unroll")                                                            \
        for (int j = 0; j < 4; j++) {                                                \
            int i = tid + j * 256;                                                   \
            int r = i >> 3, s = i & 7;                                               \
            CP_ASYNC16(_b + r * 144 + s * 16, fbase + (size_t)r * CC + _c0 + s * 4); \
        }                                                                            \
    }                                                                                \
    CP_COMMIT();                                                                     \
} while (0)

    ISSUE(0); ISSUE(1);

    uint32_t acc[4][8][2];     // [mt][nt][half] f16x2
#pragma unroll
    for (int mt = 0; mt < 4; mt++)
#pragma unroll
        for (int nt = 0; nt < 8; nt++) { acc[mt][nt][0] = 0u; acc[mt][nt][1] = 0u; }
    float nrm[4];
#pragma unroll
    for (int j = 0; j < 4; j++) nrm[j] = 0.f;

    for (int ch = 0; ch < 16; ch++) {
        int st = ch & 1;
        CP_WAIT1();
        __syncthreads();

        // ---- convert fp32 staging -> fp16 + row-norm partials ----
#pragma unroll
        for (int j = 0; j < 4; j++) {
            int i = tid + j * 256;
            int r = i >> 3, s = i & 7;
            float4 v = *(const float4*)(sm + SM_BST(st) + r * 144 + s * 16);
            __half2 h01 = __float22half2_rn(make_float2(v.x, v.y));
            __half2 h23 = __float22half2_rn(make_float2(v.z, v.w));
            uint2 u;
            u.x = *reinterpret_cast<uint32_t*>(&h01);
            u.y = *reinterpret_cast<uint32_t*>(&h23);
            *(uint2*)(sm + SM_BF16(st) + r * 80 + s * 8) = u;
            nrm[j] += v.x * v.x + v.y * v.y + v.z * v.z + v.w * v.w;
        }
        __syncthreads();

        // ---- MMA: 2 k16-steps, operands via ldmatrix ----
        uint32_t Abase = sb + (uint32_t)SM_BF16(st);
        uint32_t Bbase = sb + (uint32_t)SM_A(st);
#pragma unroll
        for (int ks = 0; ks < 2; ks++) {
            uint32_t a[4][4];
#pragma unroll
            for (int mt = 0; mt < 4; mt++) {
                uint32_t ad = Abase + (uint32_t)((m_off + mt * 16 + arow) * 80 + ks * 32 + acol);
                LDSM_X4(a[mt], ad);
            }
#pragma unroll
            for (int nt = 0; nt < 8; nt++) {
                uint32_t b0, b1;
                uint32_t bd = Bbase + (uint32_t)((n_off + nt * 8 + brow) * 80 + ks * 32 + bcol);
                LDSM_X2(b0, b1, bd);
#pragma unroll
                for (int mt = 0; mt < 4; mt++) MMA_FP16ACC(acc[mt][nt], a[mt], b0, b1);
            }
        }
        __syncthreads();
        ISSUE(ch + 2);
    }

    // ---- finalize frame row norms ----
    float* rns  = (float*)(sm + SM_RNS);
    float* snum = (float*)(sm + SM_SNUM);
    float* sden = (float*)(sm + SM_SDEN);
    float* sneg = (float*)(sm + SM_SNEG);
#pragma unroll
    for (int j = 0; j < 4; j++) {
        float v = nrm[j];
        v += __shfl_xor_sync(0xffffffffu, v, 1, 8);
        v += __shfl_xor_sync(0xffffffffu, v, 2, 8);
        v += __shfl_xor_sync(0xffffffffu, v, 4, 8);
        if ((tid & 7) == 0) rns[(tid >> 3) + j * 32] = rsqrtf(v);
    }
    snum[tid] = 0.f; snum[256 + tid] = 0.f;
    sden[tid] = 0.f; sden[256 + tid] = 0.f;
    if (tid < 4) sneg[tid] = 0.f;
    __syncthreads();

    // ---- fused sigmoid epilogue with 2-segment split ----
    int n_first = (blk * MROWS) / HWN;
    int nsplit  = (n_first + 1) * HWN - blk * MROWS;
    float qn0 = 0.f, qd0 = 0.f, qn1 = 0.f, qd1 = 0.f;

#pragma unroll
    for (int nt = 0; nt < 8; nt++) {
        float p[2][2] = {{0.f, 0.f}, {0.f, 0.f}};   // [e][seg]
        float d[2][2] = {{0.f, 0.f}, {0.f, 0.f}};
        int kbase = n_off + nt * 8 + tig * 2;
#pragma unroll
        for (int mt = 0; mt < 4; mt++) {
#pragma unroll
            for (int half = 0; half < 2; half++) {
                int row = m_off + mt * 16 + gID + half * 8;
                uint32_t pk = acc[mt][nt][half];
                float2 fv = __half22float2(*reinterpret_cast<__half2*>(&pk));
                float rn = rns[row];
                int seg = (row >= nsplit) ? 1 : 0;
                int nrow = n_first + seg;
#pragma unroll
                for (int e = 0; e < 2; e++) {
                    float S = (e ? fv.y : fv.x) * rn;
                    float wg = __fdividef(1.f, 1.f + __expf((EPS_POS_F - S) * INV_TAU));
                    p[e][seg] += wg * S;
                    d[e][seg] += wg;
                    if (kbase + e == nrow) {
                        float sp = __fdividef(1.f, 1.f + __expf((EPS_NEG_F - S) * INV_TAU));
                        float ng = 1.f - sp;
                        if (seg) { qn1 += ng * S; qd1 += ng; }
                        else     { qn0 += ng * S; qd0 += ng; }
                    }
                }
            }
        }
#pragma unroll
        for (int e = 0; e < 2; e++) {
#pragma unroll
            for (int o = 4; o < 32; o <<= 1) {
                p[e][0] += __shfl_xor_sync(0xffffffffu, p[e][0], o);
                d[e][0] += __shfl_xor_sync(0xffffffffu, d[e][0], o);
                p[e][1] += __shfl_xor_sync(0xffffffffu, p[e][1], o);
                d[e][1] += __shfl_xor_sync(0xffffffffu, d[e][1], o);
            }
            if (lane < 4) {
                int k = kbase + e;
                atomicAdd(&snum[k], p[e][0]);
                atomicAdd(&sden[k], d[e][0]);
                atomicAdd(&snum[256 + k], p[e][1]);
                atomicAdd(&sden[256 + k], d[e][1]);
            }
        }
    }
#pragma unroll
    for (int o = 1; o < 32; o <<= 1) {
        qn0 += __shfl_xor_sync(0xffffffffu, qn0, o);
        qd0 += __shfl_xor_sync(0xffffffffu, qd0, o);
        qn1 += __shfl_xor_sync(0xffffffffu, qn1, o);
        qd1 += __shfl_xor_sync(0xffffffffu, qd1, o);
    }
    if (lane == 0) {
        atomicAdd(&sneg[0], qn0); atomicAdd(&sneg[1], qd0);
        atomicAdd(&sneg[2], qn1); atomicAdd(&sneg[3], qd1);
    }
    __syncthreads();
    g_pn2[(size_t)blk * 512 + tid]       = snum[tid];
    g_pn2[(size_t)blk * 512 + 256 + tid] = snum[256 + tid];
    g_pd2[(size_t)blk * 512 + tid]       = sden[tid];
    g_pd2[(size_t)blk * 512 + 256 + tid] = sden[256 + tid];
    if (tid == 0) {
        g_qn2[blk * 2]     = sneg[0];
        g_qd2[blk * 2]     = sneg[1];
        g_qn2[blk * 2 + 1] = sneg[2];
        g_qd2[blk * 2 + 1] = sneg[3];
    }

    // ======================= fused tail (last CTA only) =====================
    __threadfence();
    __shared__ unsigned s_last;
    if (tid == 0) s_last = (atomicAdd(&g_ctr, 1u) == (unsigned)(NBLK - 1)) ? 1u : 0u;
    __syncthreads();
    if (!s_last) return;
    if (tid == 0) g_ctr = 0;       // reset for next graph replay
    __threadfence();

    // ---- phase 1: rowreduce. thread t = n. ----
    float* sE = snum;               // reuse smem: exp(Nid[k])
    {
        int n = tid;
        int r0 = n * HWN;
        int b0 = r0 >> 7;
        int b1 = (r0 + HWN - 1) >> 7;
        float qn = 0.f, qd = 0.f;
        for (int b = b0; b <= b1; b++) {
            int nf = (b << 7) / HWN;
            int seg = (n == nf) ? 0 : 1;
            qn += g_qn2[b * 2 + seg];
            qd += g_qd2[b * 2 + seg];
        }
        float sumr = 0.f, PiN = 0.f, PiD = 0.f;
        for (int k4 = 0; k4 < NN; k4 += 4) {
            float4 nu = make_float4(0.f, 0.f, 0.f, 0.f);
            float4 de = make_float4(0.f, 0.f, 0.f, 0.f);
            for (int b = b0; b <= b1; b++) {
                int nf = (b << 7) / HWN;
                int seg = (n == nf) ? 0 : 1;
                float4 a = *(const float4*)&g_pn2[(size_t)b * 512 + seg * 256 + k4];
                float4 c = *(const float4*)&g_pd2[(size_t)b * 512 + seg * 256 + k4];
                nu.x += a.x; nu.y += a.y; nu.z += a.z; nu.w += a.w;
                de.x += c.x; de.y += c.y; de.z += c.z; de.w += c.w;
            }
            float nus[4] = {nu.x, nu.y, nu.z, nu.w};
            float des[4] = {de.x, de.y, de.z, de.w};
#pragma unroll
            for (int e = 0; e < 4; e++) {
                int k = k4 + e;
                float ratio = nus[e] / des[e];
                if (k == n) { PiN = nus[e]; PiD = des[e]; sumr += ratio * (-99.f); }
                else sumr += ratio;
            }
        }
        float Pid = TEMP_F * (PiN / PiD);
        float Nid = TEMP_F * (qn / qd + sumr);
        sE[n] = __expf(Nid);
        sden[n] = __expf(-Pid);     // reuse: e^{-Pid[n]}
    }
    __syncthreads();

    // ---- phase 2: loss = (1/N) sum_{n,k} log(1 + E[k] * e^{-Pid[n]}) ----
    {
        float Pn = sden[tid];
        float acc2 = 0.f;
#pragma unroll 8
        for (int k = 0; k < NN; k++) acc2 += __logf(1.f + sE[k] * Pn);
#pragma unroll
        for (int o = 16; o; o >>= 1) acc2 += __shfl_xor_sync(0xffffffffu, acc2, o);
        __shared__ float sred2[8];
        if (lane == 0) sred2[w] = acc2;
        __syncthreads();
        if (tid == 0) {
            float s = 0.f;
#pragma unroll
            for (int i = 0; i < 8; i++) s += sred2[i];
            out[0] = s * (1.0f / NN);
        }
    }
}

extern "C" void kernel_launch(void* const* d_in, const int* in_sizes, int n_in,
                              void* d_out, int out_size) {
    const float* frame = (const float*)d_in[0];
    const float* audio = (const float*)d_in[1];
    if (n_in >= 2 && in_sizes[0] < in_sizes[1]) {
        frame = (const float*)d_in[1];
        audio = (const float*)d_in[0];
    }
    float* out = (float*)d_out;

    cudaFuncSetAttribute(k_mainTC, cudaFuncAttributeMaxDynamicSharedMemorySize, SMEM_TOTAL);

    k_audio<<<NN, 128>>>(audio);
    k_mainTC<<<NBLK, 256, SMEM_TOTAL>>>(frame, out);
}

// round 15
// speedup vs baseline: 2.9071x; 2.0495x over previous
#include <cuda_runtime.h>
#include <cuda_fp16.h>
#include <cstdint>
#include <math.h>

#define NN   256
#define HWN  196
#define CC   512
#define NBLK  392
#define MROWS 128
#define EPS_POS_F 0.65f
#define EPS_NEG_F 0.40f
#define INV_TAU   (1.0f/0.03f)
#define TEMP_F    0.07f

// ---- smem layout (bytes): 2-stage, all double-buffered ----
#define SM_A(st)    ((st) * 20480)             // audio fp16: 256 x 80B
#define SM_BST(st)  (40960 + (st) * 18432)     // frame fp32 staging: 128 x 144B
#define SM_BF16(st) (77824 + (st) * 10240)     // frame fp16: 128 x 80B
#define SM_RNS      98304                      // float[128]
#define SM_SNUM     98816                      // float[2][256]
#define SM_SDEN     100864                     // float[2][256]
#define SM_SNEG     102912                     // float[4]
#define SMEM_TOTAL  102928

// ---- scratch globals ----
__device__ __half g_aH[NN * CC];          // normalized audio fp16
__device__ float g_pn2[NBLK * 2 * NN];
__device__ float g_pd2[NBLK * 2 * NN];
__device__ float g_qn2[NBLK * 2];
__device__ float g_qd2[NBLK * 2];
__device__ float g_E[NN];                 // exp(Nid[n])
__device__ float g_P[NN];                 // exp(-Pid[n])

__device__ __forceinline__ uint32_t smem_u32(const void* p) {
    uint32_t a;
    asm("{ .reg .u64 t; cvta.to.shared.u64 t, %1; cvt.u32.u64 %0, t; }" : "=r"(a) : "l"(p));
    return a;
}

#define CP_ASYNC16(dst, src) \
    asm volatile("cp.async.cg.shared.global [%0], [%1], 16;" :: "r"(dst), "l"(src) : "memory")
#define CP_COMMIT() asm volatile("cp.async.commit_group;" ::: "memory")
#define CP_WAIT1()  asm volatile("cp.async.wait_group 1;" ::: "memory")

// fp16 MMA with fp16 accumulators
#define MMA_FP16ACC(d, a, b0, b1)                                               \
    asm volatile("mma.sync.aligned.m16n8k16.row.col.f16.f16.f16.f16 "           \
        "{%0,%1}, {%2,%3,%4,%5}, {%6,%7}, {%0,%1};"                             \
        : "+r"((d)[0]), "+r"((d)[1])                                            \
        : "r"((a)[0]), "r"((a)[1]), "r"((a)[2]), "r"((a)[3]), "r"(b0), "r"(b1))

#define LDSM_X4(r, addr)                                                        \
    asm volatile("ldmatrix.sync.aligned.m8n8.x4.shared.b16 {%0,%1,%2,%3}, [%4];" \
        : "=r"((r)[0]), "=r"((r)[1]), "=r"((r)[2]), "=r"((r)[3]) : "r"(addr))

#define LDSM_X2(r0, r1, addr)                                                   \
    asm volatile("ldmatrix.sync.aligned.m8n8.x2.shared.b16 {%0,%1}, [%2];"      \
        : "=r"(r0), "=r"(r1) : "r"(addr))

// ---------------------------------------------------------------------------
// Kernel A: normalize audio -> fp16 row-major [k][c]
// ---------------------------------------------------------------------------
__global__ void k_audio(const float* __restrict__ audio) {
    int k = blockIdx.x;
    int tid = threadIdx.x;  // 128
    float4 v = *(const float4*)(audio + (size_t)k * CC + tid * 4);
    float ss = v.x * v.x + v.y * v.y + v.z * v.z + v.w * v.w;
#pragma unroll
    for (int o = 16; o; o >>= 1) ss += __shfl_xor_sync(0xffffffffu, ss, o);
    __shared__ float sred[4];
    if ((tid & 31) == 0) sred[tid >> 5] = ss;
    __syncthreads();
    float rn = rsqrtf(sred[0] + sred[1] + sred[2] + sred[3]);
    __half2 p0 = __float22half2_rn(make_float2(v.x * rn, v.y * rn));
    __half2 p1 = __float22half2_rn(make_float2(v.z * rn, v.w * rn));
    uint2 u;
    u.x = *reinterpret_cast<uint32_t*>(&p0);
    u.y = *reinterpret_cast<uint32_t*>(&p1);
    *(uint2*)(g_aH + (size_t)k * CC + tid * 4) = u;
}

// ---------------------------------------------------------------------------
// Main: CTA b computes S[flat rows b*128..+128, audio 0..255] via fp16 MMA,
// fused sigmoid reductions. (Round-10 structure: NO in-kernel tail — the
// fused-tail variants spilled the mainloop to 128 regs; see rounds 12-13.)
// ---------------------------------------------------------------------------
__global__ void __launch_bounds__(256) k_mainTC(const float* __restrict__ frame) {
    extern __shared__ char sm[];
    uint32_t sb = smem_u32(sm);
    int tid = threadIdx.x;
    int lane = tid & 31;
    int w = tid >> 5;
    int gID = lane >> 2;
    int tig = lane & 3;
    int blk = blockIdx.x;          // 0..391

    const float* fbase = frame + (size_t)blk * MROWS * CC;
    int m_off = (w >> 2) * 64;     // 2 m-groups of 64 rows
    int n_off = (w & 3) * 64;      // 4 n-groups of 64 audio cols

    // ldmatrix per-lane row/col selectors
    int arow = (lane & 7) + ((lane >> 3) & 1) * 8;
    int acol = (lane >> 4) * 16;
    int brow = lane & 7;
    int bcol = ((lane >> 3) & 1) * 16;

#define ISSUE(CH) do {                                                              \
    int _c = (CH);                                                                   \
    if (_c < 16) {                                                                   \
        int _st = _c & 1;                                                            \
        int _c0 = _c * 32;                                                           \
        uint32_t _a = sb + SM_A(_st);                                                \
        uint32_t _b = sb + SM_BST(_st);                                              \
        _Pragma("unroll")                                                            \
        for (int j = 0; j < 4; j++) {                                                \
            int i = tid + j * 256;                                                   \
            int r = i >> 2, s = i & 3;                                               \
            CP_ASYNC16(_a + r * 80 + s * 16, g_aH + (size_t)r * CC + _c0 + s * 8);   \
        }                                                                            \
        _Pragma("unroll")                                                            \
        for (int j = 0; j < 4; j++) {                                                \
            int i = tid + j * 256;                                                   \
            int r = i >> 3, s = i & 7;                                               \
            CP_ASYNC16(_b + r * 144 + s * 16, fbase + (size_t)r * CC + _c0 + s * 4); \
        }                                                                            \
    }                                                                                \
    CP_COMMIT();                                                                     \
} while (0)

    ISSUE(0); ISSUE(1);

    uint32_t acc[4][8][2];     // [mt][nt][half] f16x2
#pragma unroll
    for (int mt = 0; mt < 4; mt++)
#pragma unroll
        for (int nt = 0; nt < 8; nt++) { acc[mt][nt][0] = 0u; acc[mt][nt][1] = 0u; }
    float nrm[4];
#pragma unroll
    for (int j = 0; j < 4; j++) nrm[j] = 0.f;

    for (int ch = 0; ch < 16; ch++) {
        int st = ch & 1;
        CP_WAIT1();
        __syncthreads();

        // ---- convert fp32 staging -> fp16 + row-norm partials ----
#pragma unroll
        for (int j = 0; j < 4; j++) {
            int i = tid + j * 256;
            int r = i >> 3, s = i & 7;
            float4 v = *(const float4*)(sm + SM_BST(st) + r * 144 + s * 16);
            __half2 h01 = __float22half2_rn(make_float2(v.x, v.y));
            __half2 h23 = __float22half2_rn(make_float2(v.z, v.w));
            uint2 u;
            u.x = *reinterpret_cast<uint32_t*>(&h01);
            u.y = *reinterpret_cast<uint32_t*>(&h23);
            *(uint2*)(sm + SM_BF16(st) + r * 80 + s * 8) = u;
            nrm[j] += v.x * v.x + v.y * v.y + v.z * v.z + v.w * v.w;
        }
        __syncthreads();

        // ---- MMA: 2 k16-steps, operands via ldmatrix ----
        uint32_t Abase = sb + (uint32_t)SM_BF16(st);
        uint32_t Bbase = sb + (uint32_t)SM_A(st);
#pragma unroll
        for (int ks = 0; ks < 2; ks++) {
            uint32_t a[4][4];
#pragma unroll
            for (int mt = 0; mt < 4; mt++) {
                uint32_t ad = Abase + (uint32_t)((m_off + mt * 16 + arow) * 80 + ks * 32 + acol);
                LDSM_X4(a[mt], ad);
            }
#pragma unroll
            for (int nt = 0; nt < 8; nt++) {
                uint32_t b0, b1;
                uint32_t bd = Bbase + (uint32_t)((n_off + nt * 8 + brow) * 80 + ks * 32 + bcol);
                LDSM_X2(b0, b1, bd);
#pragma unroll
                for (int mt = 0; mt < 4; mt++) MMA_FP16ACC(acc[mt][nt], a[mt], b0, b1);
            }
        }
        __syncthreads();
        ISSUE(ch + 2);
    }

    // ---- finalize frame row norms ----
    float* rns  = (float*)(sm + SM_RNS);
    float* snum = (float*)(sm + SM_SNUM);
    float* sden = (float*)(sm + SM_SDEN);
    float* sneg = (float*)(sm + SM_SNEG);
#pragma unroll
    for (int j = 0; j < 4; j++) {
        float v = nrm[j];
        v += __shfl_xor_sync(0xffffffffu, v, 1, 8);
        v += __shfl_xor_sync(0xffffffffu, v, 2, 8);
        v += __shfl_xor_sync(0xffffffffu, v, 4, 8);
        if ((tid & 7) == 0) rns[(tid >> 3) + j * 32] = rsqrtf(v);
    }
    snum[tid] = 0.f; snum[256 + tid] = 0.f;
    sden[tid] = 0.f; sden[256 + tid] = 0.f;
    if (tid < 4) sneg[tid] = 0.f;
    __syncthreads();

    // ---- fused sigmoid epilogue with 2-segment split ----
    int n_first = (blk * MROWS) / HWN;
    int nsplit  = (n_first + 1) * HWN - blk * MROWS;
    float qn0 = 0.f, qd0 = 0.f, qn1 = 0.f, qd1 = 0.f;

#pragma unroll
    for (int nt = 0; nt < 8; nt++) {
        float p[2][2] = {{0.f, 0.f}, {0.f, 0.f}};   // [e][seg]
        float d[2][2] = {{0.f, 0.f}, {0.f, 0.f}};
        int kbase = n_off + nt * 8 + tig * 2;
#pragma unroll
        for (int mt = 0; mt < 4; mt++) {
#pragma unroll
            for (int half = 0; half < 2; half++) {
                int row = m_off + mt * 16 + gID + half * 8;
                uint32_t pk = acc[mt][nt][half];
                float2 fv = __half22float2(*reinterpret_cast<__half2*>(&pk));
                float rn = rns[row];
                int seg = (row >= nsplit) ? 1 : 0;
                int nrow = n_first + seg;
#pragma unroll
                for (int e = 0; e < 2; e++) {
                    float S = (e ? fv.y : fv.x) * rn;
                    float wg = __fdividef(1.f, 1.f + __expf((EPS_POS_F - S) * INV_TAU));
                    p[e][seg] += wg * S;
                    d[e][seg] += wg;
                    if (kbase + e == nrow) {
                        float sp = __fdividef(1.f, 1.f + __expf((EPS_NEG_F - S) * INV_TAU));
                        float ng = 1.f - sp;
                        if (seg) { qn1 += ng * S; qd1 += ng; }
                        else     { qn0 += ng * S; qd0 += ng; }
                    }
                }
            }
        }
#pragma unroll
        for (int e = 0; e < 2; e++) {
#pragma unroll
            for (int o = 4; o < 32; o <<= 1) {
                p[e][0] += __shfl_xor_sync(0xffffffffu, p[e][0], o);
                d[e][0] += __shfl_xor_sync(0xffffffffu, d[e][0], o);
                p[e][1] += __shfl_xor_sync(0xffffffffu, p[e][1], o);
                d[e][1] += __shfl_xor_sync(0xffffffffu, d[e][1], o);
            }
            if (lane < 4) {
                int k = kbase + e;
                atomicAdd(&snum[k], p[e][0]);
                atomicAdd(&sden[k], d[e][0]);
                atomicAdd(&snum[256 + k], p[e][1]);
                atomicAdd(&sden[256 + k], d[e][1]);
            }
        }
    }
#pragma unroll
    for (int o = 1; o < 32; o <<= 1) {
        qn0 += __shfl_xor_sync(0xffffffffu, qn0, o);
        qd0 += __shfl_xor_sync(0xffffffffu, qd0, o);
        qn1 += __shfl_xor_sync(0xffffffffu, qn1, o);
        qd1 += __shfl_xor_sync(0xffffffffu, qd1, o);
    }
    if (lane == 0) {
        atomicAdd(&sneg[0], qn0); atomicAdd(&sneg[1], qd0);
        atomicAdd(&sneg[2], qn1); atomicAdd(&sneg[3], qd1);
    }
    __syncthreads();
    g_pn2[(size_t)blk * 512 + tid]       = snum[tid];
    g_pn2[(size_t)blk * 512 + 256 + tid] = snum[256 + tid];
    g_pd2[(size_t)blk * 512 + tid]       = sden[tid];
    g_pd2[(size_t)blk * 512 + 256 + tid] = sden[256 + tid];
    if (tid == 0) {
        g_qn2[blk * 2]     = sneg[0];
        g_qd2[blk * 2]     = sneg[1];
        g_qn2[blk * 2 + 1] = sneg[2];
        g_qd2[blk * 2 + 1] = sneg[3];
    }
}

// ---------------------------------------------------------------------------
// Kernel D: gather per-block partials -> store exp(Nid), exp(-Pid).
// Also zeroes out[0] for the k_loss_part atomic accumulation.
// ---------------------------------------------------------------------------
__global__ void k_rowreduce(float* __restrict__ out) {
    int n = blockIdx.x;
    int tid = threadIdx.x;   // 256 = k
    if (n == 0 && tid == 0) out[0] = 0.f;
    int r0 = n * HWN;
    int b0 = r0 >> 7;
    int b1 = (r0 + HWN - 1) >> 7;
    float num = 0.f, den = 0.f, qn = 0.f, qd = 0.f;
    for (int b = b0; b <= b1; b++) {
        int nf = (b << 7) / HWN;
        int seg = (n == nf) ? 0 : 1;
        num += g_pn2[(size_t)b * 512 + seg * 256 + tid];
        den += g_pd2[(size_t)b * 512 + seg * 256 + tid];
        qn  += g_qn2[b * 2 + seg];
        qd  += g_qd2[b * 2 + seg];
    }
    float ratio = num / den;
    __shared__ float sPi[2];
    if (tid == n) { sPi[0] = num; sPi[1] = den; }
    float contrib = (tid == n) ? ratio * (-99.f) : ratio;
#pragma unroll
    for (int o = 16; o; o >>= 1) contrib += __shfl_xor_sync(0xffffffffu, contrib, o);
    __shared__ float sred[8];
    if ((tid & 31) == 0) sred[tid >> 5] = contrib;
    __syncthreads();
    if (tid == 0) {
        float r = 0.f;
#pragma unroll
        for (int i = 0; i < 8; i++) r += sred[i];
        float Pi = sPi[0] / sPi[1];
        float Nh = qn / qd;
        float Pid = TEMP_F * Pi;
        float Nid = TEMP_F * (Nh + r);
        g_E[n] = __expf(Nid);       // exp(Ni_d[n])
        g_P[n] = __expf(-Pid);      // exp(-Pi_d[n])
    }
}

// ---------------------------------------------------------------------------
// Kernel E: loss = (1/N) sum_{n,k} log(1 + E[k] * P[n])   (factorized
// softplus(Nid[k]-Pid[n]): 1 MUFU per pair). atomicAdd into out.
// ---------------------------------------------------------------------------
__global__ void k_loss_part(float* __restrict__ out) {
    int tid = threadIdx.x;   // 256 = 8 warps; warp w -> n = blk*8 + w
    int lane = tid & 31;
    int w = tid >> 5;
    __shared__ float sE[256];
    sE[tid] = g_E[tid];
    __syncthreads();
    int n = blockIdx.x * 8 + w;
    float Pn = g_P[n];
    float acc = 0.f;
#pragma unroll
    for (int kk = 0; kk < 8; kk++)
        acc += __logf(1.f + sE[lane + kk * 32] * Pn);
#pragma unroll
    for (int o = 16; o; o >>= 1) acc += __shfl_xor_sync(0xffffffffu, acc, o);
    __shared__ float sred[8];
    if (lane == 0) sred[w] = acc;
    __syncthreads();
    if (tid == 0) {
        float s = 0.f;
#pragma unroll
        for (int i = 0; i < 8; i++) s += sred[i];
        atomicAdd(out, s * (1.0f / NN));
    }
}

extern "C" void kernel_launch(void* const* d_in, const int* in_sizes, int n_in,
                              void* d_out, int out_size) {
    const float* frame = (const float*)d_in[0];
    const float* audio = (const float*)d_in[1];
    if (n_in >= 2 && in_sizes[0] < in_sizes[1]) {
        frame = (const float*)d_in[1];
        audio = (const float*)d_in[0];
    }
    float* out = (float*)d_out;

    cudaFuncSetAttribute(k_mainTC, cudaFuncAttributeMaxDynamicSharedMemorySize, SMEM_TOTAL);

    k_audio<<<NN, 128>>>(audio);
    k_mainTC<<<NBLK, 256, SMEM_TOTAL>>>(frame);
    k_rowreduce<<<NN, 256>>>(out);
    k_loss_part<<<32, 256>>>(out);
}